// round 1
// baseline (speedup 1.0000x reference)
#include <cuda_runtime.h>
#include <math.h>

#define BB 2
#define SS 2048
#define HH 32
#define DD 32
#define DM (HH*DD)        // 1024
#define QKV_COLS (3*DM)   // 3072
#define ROWS (BB*SS)      // 4096
#define KDIM DM           // 1024 (GEMM K)

// scratch: qkv = x @ W_qkv, RoPE'd in place.  ~50.3 MB static device array.
__device__ float g_qkv[(size_t)ROWS * QKV_COLS];

// ---------------------------------------------------------------------------
// Kernel 1: fp32 SGEMM  C[4096,3072] = A[4096,1024] @ W[1024,3072]
// 128x128 block tile, BK=8, 256 threads, 8x8 microtile.
// ---------------------------------------------------------------------------
__global__ __launch_bounds__(256) void sgemm_qkv(const float* __restrict__ A,
                                                 const float* __restrict__ W,
                                                 float* __restrict__ C) {
    __shared__ float As[8][128];   // transposed A tile
    __shared__ float Bs[8][128];

    const int N = QKV_COLS;
    const int K = KDIM;
    int tid  = threadIdx.x;
    int brow = blockIdx.y * 128;   // M offset
    int bcol = blockIdx.x * 128;   // N offset

    // A-tile load mapping: 128x8 floats, 1 float4 per thread
    int arow = tid >> 1;           // 0..127
    int acol = (tid & 1) * 4;      // 0 or 4
    // B-tile load mapping: 8x128 floats, 1 float4 per thread
    int brl  = tid >> 5;           // 0..7
    int bcl  = (tid & 31) * 4;     // 0..124

    const float* Aptr = A + (size_t)(brow + arow) * K + acol;
    const float* Bptr = W + (size_t)brl * N + bcol + bcl;

    int ty = tid >> 4;             // 0..15
    int tx = tid & 15;             // 0..15

    float acc[8][8];
    #pragma unroll
    for (int i = 0; i < 8; i++)
        #pragma unroll
        for (int j = 0; j < 8; j++) acc[i][j] = 0.f;

    for (int k0 = 0; k0 < K; k0 += 8) {
        float4 av = *(const float4*)(Aptr + k0);
        float4 bv = *(const float4*)(Bptr + (size_t)k0 * N);
        As[acol + 0][arow] = av.x;
        As[acol + 1][arow] = av.y;
        As[acol + 2][arow] = av.z;
        As[acol + 3][arow] = av.w;
        *(float4*)&Bs[brl][bcl] = bv;
        __syncthreads();

        #pragma unroll
        for (int k = 0; k < 8; k++) {
            float ar[8], br[8];
            *(float4*)&ar[0] = *(const float4*)&As[k][ty * 8];
            *(float4*)&ar[4] = *(const float4*)&As[k][ty * 8 + 4];
            *(float4*)&br[0] = *(const float4*)&Bs[k][tx * 8];
            *(float4*)&br[4] = *(const float4*)&Bs[k][tx * 8 + 4];
            #pragma unroll
            for (int i = 0; i < 8; i++)
                #pragma unroll
                for (int j = 0; j < 8; j++)
                    acc[i][j] = fmaf(ar[i], br[j], acc[i][j]);
        }
        __syncthreads();
    }

    #pragma unroll
    for (int i = 0; i < 8; i++) {
        int r = brow + ty * 8 + i;
        float* Crow = C + (size_t)r * N + bcol + tx * 8;
        *(float4*)(Crow)     = make_float4(acc[i][0], acc[i][1], acc[i][2], acc[i][3]);
        *(float4*)(Crow + 4) = make_float4(acc[i][4], acc[i][5], acc[i][6], acc[i][7]);
    }
}

// ---------------------------------------------------------------------------
// Kernel 2: RoPE in place on q and k slices of qkv.
// One warp per (b,s,h); lane = dim d. Rotate-half partner via shfl_xor(16).
// NOTE: reference uses arange(0, D)/D (full dim) for inv_freq.
// ---------------------------------------------------------------------------
__global__ __launch_bounds__(256) void rope_kernel(float* __restrict__ qkv) {
    int wid  = (blockIdx.x * blockDim.x + threadIdx.x) >> 5;  // 0 .. B*S*H-1
    int lane = threadIdx.x & 31;
    if (wid >= BB * SS * HH) return;
    int h  = wid % HH;
    int bs = wid / HH;          // b*S + s
    int s  = bs % SS;

    float inv_freq = powf(10000.0f, -(float)lane / (float)DD);
    float sv, cv;
    sincosf((float)s * inv_freq, &sv, &cv);

    float* qp = qkv + (size_t)bs * QKV_COLS + h * DD + lane;
    float* kp = qp + DM;
    float q = *qp;
    float k = *kp;
    float qpart = __shfl_xor_sync(0xffffffff, q, 16);
    float kpart = __shfl_xor_sync(0xffffffff, k, 16);
    float qrot = (lane < 16) ? -qpart : qpart;
    float krot = (lane < 16) ? -kpart : kpart;
    *qp = fmaf(q, cv, qrot * sv);
    *kp = fmaf(k, cv, krot * sv);
}

// ---------------------------------------------------------------------------
// Kernel 3: causal flash attention, fp32, D=32.
// Block = 128 threads; one thread owns one query row (BQ=128).
// Key/Value tiles of 128 rows in smem; chunked (16-key) online softmax.
// grid = (S/BQ, B*H)
// ---------------------------------------------------------------------------
#define BQ 128
#define BK 128

__global__ __launch_bounds__(128) void flash_kernel(const float* __restrict__ qkv,
                                                    float* __restrict__ out) {
    __shared__ float Ks[BK][DD];
    __shared__ float Vs[BK][DD];

    int t  = threadIdx.x;
    int bh = blockIdx.y;
    int b  = bh >> 5;
    int h  = bh & 31;
    int i0 = blockIdx.x * BQ;
    int r  = i0 + t;                       // this thread's global query row

    const float scale = 0.17677669529663687f;  // 1/sqrt(32)

    // load pre-scaled q row into registers
    float q[DD];
    {
        const float* qrow = qkv + (size_t)(b * SS + r) * QKV_COLS + h * DD;
        #pragma unroll
        for (int i = 0; i < 8; i++) {
            float4 v4 = *(const float4*)(qrow + i * 4);
            q[i*4+0] = v4.x * scale;
            q[i*4+1] = v4.y * scale;
            q[i*4+2] = v4.z * scale;
            q[i*4+3] = v4.w * scale;
        }
    }

    float o[DD];
    #pragma unroll
    for (int d = 0; d < DD; d++) o[d] = 0.f;
    float m = -1e30f;
    float l = 0.f;

    int ntiles = blockIdx.x + 1;   // causal: tiles 0..blockIdx.x
    for (int tile = 0; tile < ntiles; tile++) {
        int j0 = tile * BK;
        // cooperative K/V tile load: thread t loads key row j0+t
        {
            const float* krow = qkv + (size_t)(b * SS + j0 + t) * QKV_COLS + DM + h * DD;
            const float* vrow = krow + DM;
            #pragma unroll
            for (int i = 0; i < 8; i++) {
                *(float4*)&Ks[t][i * 4] = *(const float4*)(krow + i * 4);
                *(float4*)&Vs[t][i * 4] = *(const float4*)(vrow + i * 4);
            }
        }
        __syncthreads();

        // causal key limit within this tile (tiles are BQ==BK aligned):
        int kl = (tile == blockIdx.x) ? (t + 1) : BK;

        for (int c0 = 0; c0 < kl; c0 += 16) {
            float sreg[16];
            float cmax = m;
            #pragma unroll
            for (int c = 0; c < 16; c++) {
                int kk = c0 + c;   // c0 <= 112 always, so kk <= 127: in bounds
                float s_ = 0.f;
                const float4* kr = (const float4*)&Ks[kk][0];
                #pragma unroll
                for (int i = 0; i < 8; i++) {
                    float4 kv = kr[i];
                    s_ = fmaf(q[i*4+0], kv.x, s_);
                    s_ = fmaf(q[i*4+1], kv.y, s_);
                    s_ = fmaf(q[i*4+2], kv.z, s_);
                    s_ = fmaf(q[i*4+3], kv.w, s_);
                }
                s_ = (kk < kl) ? s_ : -3.0e38f;   // causal mask inside chunk
                sreg[c] = s_;
                cmax = fmaxf(cmax, s_);
            }
            float alpha = __expf(m - cmax);
            m = cmax;
            l *= alpha;
            #pragma unroll
            for (int d = 0; d < DD; d++) o[d] *= alpha;
            #pragma unroll
            for (int c = 0; c < 16; c++) {
                float p = __expf(sreg[c] - m);
                l += p;
                const float4* vr = (const float4*)&Vs[c0 + c][0];
                #pragma unroll
                for (int i = 0; i < 8; i++) {
                    float4 vv = vr[i];
                    o[i*4+0] = fmaf(p, vv.x, o[i*4+0]);
                    o[i*4+1] = fmaf(p, vv.y, o[i*4+1]);
                    o[i*4+2] = fmaf(p, vv.z, o[i*4+2]);
                    o[i*4+3] = fmaf(p, vv.w, o[i*4+3]);
                }
            }
        }
        __syncthreads();
    }

    float inv_l = 1.0f / l;
    float* orow = out + (size_t)(b * SS + r) * DM + h * DD;
    #pragma unroll
    for (int i = 0; i < 8; i++) {
        *(float4*)(orow + i * 4) = make_float4(o[i*4+0] * inv_l, o[i*4+1] * inv_l,
                                               o[i*4+2] * inv_l, o[i*4+3] * inv_l);
    }
}

// ---------------------------------------------------------------------------
// Launch
// ---------------------------------------------------------------------------
extern "C" void kernel_launch(void* const* d_in, const int* in_sizes, int n_in,
                              void* d_out, int out_size) {
    const float* x = (const float*)d_in[0];   // [2,2048,1024]
    const float* W = (const float*)d_in[1];   // [1024,3072]
    // d_in[2] = mask: deterministic causal tril; implemented structurally.
    float* out = (float*)d_out;               // [2,2048,1024]

    float* qkv = nullptr;
    cudaGetSymbolAddress((void**)&qkv, g_qkv);

    // 1) QKV projection
    dim3 ggrid(QKV_COLS / 128, ROWS / 128);   // (24, 32)
    sgemm_qkv<<<ggrid, 256>>>(x, W, qkv);

    // 2) RoPE on q,k (in place)
    int nwarp = BB * SS * HH;                 // 131072
    rope_kernel<<<nwarp / 8, 256>>>(qkv);     // 8 warps per block

    // 3) causal flash attention
    dim3 fgrid(SS / BQ, BB * HH);             // (16, 64)
    flash_kernel<<<fgrid, 128>>>(qkv, out);
}